// round 2
// baseline (speedup 1.0000x reference)
#include <cuda_runtime.h>

// AttentionLite on GB300 — round 2 (fix output scramble permutation)
// B=4, G=8, HEADS=4, C=32 per group, H=W=32, K=7, P=3 -> padded 38x38
// m-dimension = G*K*K = 392 (softmax window shared across query groups)
//
// Reference epilogue: transpose(0,4,2,3,1)+reshape scrambles axes:
//   out_final[b, g*32 + h, w, c] = O[b, c, h, w, g]

#define NB   4
#define NG   8
#define NHD  4
#define CW   32          // OUT_W == IN_W
#define HH   32
#define WW   32
#define KS   7
#define PD   3
#define HP   38          // H + 2*P
#define NM   392         // G*K*K
#define MPAD 416         // padded m (104 float4 tiles)
#define MSK  424         // smem stride for K/S rows (16B-aligned, conflict-free fill)
#define MSV  417         // smem stride for V rows (odd -> conflict-free column reads)
#define NPIX (HH*WW)

#define ATTN_SMEM ((32*MSK + 32*MSV + 1024 + 32) * 4)   // = 111872 bytes

// ---------------- scratch (no allocs allowed) ----------------
__device__ float g_q[NB*NPIX*1024];      // [b][p][c][r], r = h*8+g   (16 MB)
__device__ float g_k[NB*HP*HP*256];      // [b][sy][sx][c][g']        (5.9 MB)
__device__ float g_v[NB*HP*HP*256];

// ---------------- q conv: q[b,p,c,h,g] = sum_i x[b,g*32+i,p]*wq[g,h*32+c,i]+bq ----------------
__global__ void __launch_bounds__(256) qconv_kernel(const float* __restrict__ x,
                                                    const float* __restrict__ wq,
                                                    const float* __restrict__ bq) {
    int bp = blockIdx.x;               // b*1024 + p
    int b = bp >> 10, p = bp & 1023;
    __shared__ float xs[256];          // xs[i*8+g] = x[b, g*32+i, p]
    int t = threadIdx.x;
    {
        float v = x[(b*256 + t)*1024 + p];
        xs[(t & 31)*8 + (t >> 5)] = v;
    }
    __syncthreads();
    int g = t & 7, hh = (t >> 3) & 3, c0 = t >> 5;
    float acc[4];
    const float4* w4[4];
    #pragma unroll
    for (int k = 0; k < 4; k++) {
        int c = c0 + 8*k;
        int o = g*128 + hh*32 + c;
        acc[k] = bq[o];
        w4[k] = (const float4*)(wq + o*32);
    }
    #pragma unroll
    for (int i4 = 0; i4 < 8; i4++) {
        float xv0 = xs[(i4*4+0)*8 + g];
        float xv1 = xs[(i4*4+1)*8 + g];
        float xv2 = xs[(i4*4+2)*8 + g];
        float xv3 = xs[(i4*4+3)*8 + g];
        #pragma unroll
        for (int k = 0; k < 4; k++) {
            float4 w = w4[k][i4];
            acc[k] += xv0*w.x + xv1*w.y + xv2*w.z + xv3*w.w;
        }
    }
    #pragma unroll
    for (int k = 0; k < 4; k++) {
        int idx = (c0 + 8*k)*32 + hh*8 + g;     // [c][r]
        g_q[bp*1024 + idx] = acc[k];
    }
}

// ---------------- k/v conv on padded grid (bias at padded locations too) ----------------
__global__ void __launch_bounds__(256) kvconv_kernel(const float* __restrict__ x,
                                                     const float* __restrict__ wk,
                                                     const float* __restrict__ bk,
                                                     const float* __restrict__ wv,
                                                     const float* __restrict__ bv) {
    int bp = blockIdx.x;                       // b*1444 + sy*38 + sx
    int b = bp / (HP*HP);
    int sp = bp - b*(HP*HP);
    int sy = sp / HP, sx = sp - sy*HP;
    int iy = sy - PD, ix = sx - PD;
    bool inb = (iy >= 0) && (iy < HH) && (ix >= 0) && (ix < WW);
    __shared__ float xs[256];                  // xs[i*8+g]
    int t = threadIdx.x;
    {
        float v = inb ? x[(b*256 + t)*1024 + iy*32 + ix] : 0.f;
        xs[(t & 31)*8 + (t >> 5)] = v;
    }
    __syncthreads();
    int c = t >> 3, g = t & 7;
    const float4* wk4 = (const float4*)(wk + (g*32 + c)*32);
    const float4* wv4 = (const float4*)(wv + (g*32 + c)*32);
    float ak = bk[g*32 + c], av = bv[g*32 + c];
    #pragma unroll
    for (int i4 = 0; i4 < 8; i4++) {
        float xv0 = xs[(i4*4+0)*8 + g];
        float xv1 = xs[(i4*4+1)*8 + g];
        float xv2 = xs[(i4*4+2)*8 + g];
        float xv3 = xs[(i4*4+3)*8 + g];
        float4 a = wk4[i4];
        float4 bw = wv4[i4];
        ak += xv0*a.x + xv1*a.y + xv2*a.z + xv3*a.w;
        av += xv0*bw.x + xv1*bw.y + xv2*bw.z + xv3*bw.w;
    }
    g_k[bp*256 + c*8 + g] = ak;                // [c][g'] (g' fastest)
    g_v[bp*256 + c*8 + g] = av;
}

// ---------------- attention: one CTA per (b, pixel) ----------------
__device__ __forceinline__ void s_compute_tile(const float* Ks, const float* qs,
                                               int mtile, int ty, float* a) {
    #pragma unroll
    for (int u = 0; u < 16; u++) a[u] = 0.f;
    int mcol = mtile * 4;
    #pragma unroll
    for (int cc = 0; cc < 32; cc++) {
        float4 kv = *(const float4*)(Ks + cc*MSK + mcol);
        float4 qv = *(const float4*)(qs + cc*32 + 4*ty);
        a[0]  += qv.x*kv.x; a[1]  += qv.x*kv.y; a[2]  += qv.x*kv.z; a[3]  += qv.x*kv.w;
        a[4]  += qv.y*kv.x; a[5]  += qv.y*kv.y; a[6]  += qv.y*kv.z; a[7]  += qv.y*kv.w;
        a[8]  += qv.z*kv.x; a[9]  += qv.z*kv.y; a[10] += qv.z*kv.z; a[11] += qv.z*kv.w;
        a[12] += qv.w*kv.x; a[13] += qv.w*kv.y; a[14] += qv.w*kv.z; a[15] += qv.w*kv.w;
    }
}

__device__ __forceinline__ void s_store_tile(float* Ks, int mtile, int ty, const float* a) {
    int mcol = mtile * 4;
    #pragma unroll
    for (int rr = 0; rr < 4; rr++) {
        float4 v = make_float4(a[rr*4+0], a[rr*4+1], a[rr*4+2], a[rr*4+3]);
        *(float4*)(Ks + (4*ty + rr)*MSK + mcol) = v;
    }
}

__global__ void __launch_bounds__(256, 2) attn_kernel(const float* __restrict__ rel_h,
                                                      const float* __restrict__ rel_w,
                                                      float* __restrict__ out) {
    extern __shared__ float sm[];
    float* Ks   = sm;                       // [32 c][MSK] K(+rel); reused as S [32 r][MSK]
    float* Vs   = sm + 32*MSK;              // [32 c][MSV]
    float* qs   = Vs + 32*MSV;              // [32 c][32 r]
    float* rinv = qs + 1024;                // [32]

    int bp = blockIdx.x;
    int b = bp >> 10, p = bp & 1023;
    int px = p >> 5, py = p & 31;           // px = h (row), py = w (col)
    int t = threadIdx.x;
    int tx = t & 31, ty = t >> 5;

    // stage q (contiguous [c][r] layout)
    ((float4*)qs)[t] = ((const float4*)(g_q + bp*1024))[t];

    // stage K window (+rel) and V window
    {
        int c = t >> 3, gq = t & 7;
        float rh[KS];
        #pragma unroll
        for (int u = 0; u < KS; u++)
            rh[u] = (c < 16) ? rel_h[c*56 + gq*7 + u] : rel_w[(c-16)*56 + gq*7 + u];
        const float* kbase = g_k + ((b*HP + px)*HP + py)*256 + t;
        const float* vbase = g_v + ((b*HP + px)*HP + py)*256 + t;
        for (int i = 0; i < KS; i++) {
            #pragma unroll
            for (int j = 0; j < KS; j++) {
                int m = gq*49 + i*7 + j;
                int off = (i*HP + j)*256;
                float rel = (c < 16) ? rh[i] : rh[j];
                Ks[c*MSK + m] = kbase[off] + rel;
                Vs[c*MSV + m] = vbase[off];
            }
        }
        if (t < 32) {
            for (int m = NM; m < MPAD; m++) Ks[t*MSK + m] = 0.f;
        }
    }
    __syncthreads();

    // S = q^T (32r x 32c) * K (32c x 416m), 4x4 register tiles.
    // Double-buffered so S can overwrite the K smem region column-range by column-range.
    float acc[2][16];
    s_compute_tile(Ks, qs, tx, ty, acc[0]);
    #pragma unroll
    for (int k = 1; k < 4; k++) {
        __syncthreads();
        if (tx + 32*k < 104) s_compute_tile(Ks, qs, tx + 32*k, ty, acc[k & 1]);
        s_store_tile(Ks, tx + 32*(k-1), ty, acc[(k-1) & 1]);
    }
    __syncthreads();
    if (tx + 96 < 104) s_store_tile(Ks, tx + 96, ty, acc[1]);
    __syncthreads();

    // softmax per row r over m in [0, 392); warp ty does rows 4ty..4ty+3
    #pragma unroll
    for (int rr = 0; rr < 4; rr++) {
        int r = ty*4 + rr;
        float* Srow = Ks + r*MSK;
        float mx = -1e30f;
        for (int m = tx; m < NM; m += 32) mx = fmaxf(mx, Srow[m]);
        #pragma unroll
        for (int off = 16; off; off >>= 1) mx = fmaxf(mx, __shfl_xor_sync(0xffffffffu, mx, off));
        float sum = 0.f;
        for (int m = tx; m < NM; m += 32) {
            float e = __expf(Srow[m] - mx);
            Srow[m] = e;
            sum += e;
        }
        #pragma unroll
        for (int off = 16; off; off >>= 1) sum += __shfl_xor_sync(0xffffffffu, sum, off);
        if (tx == 0) rinv[r] = 1.f / sum;
    }
    __syncthreads();

    // head-collapse: Ag[g][m] = sum_h attn[h*8+g][m] (normalized), written in place to rows 0..7
    for (int idx = t; idx < 8*NM; idx += 256) {
        int g = idx / NM;
        int m = idx - g*NM;
        float s = 0.f;
        #pragma unroll
        for (int hh = 0; hh < 4; hh++) {
            int r = hh*8 + g;
            s += Ks[r*MSK + m] * rinv[r];
        }
        Ks[g*MSK + m] = s;
    }
    __syncthreads();

    // O[c][g] = sum_m Ag[g][m] * V[c][m];  thread = (c=tx, g=ty)
    // Reference epilogue scramble: out[b, g*32 + h, w, c] = O[b, c, h, w, g]
    {
        int c = tx, g = ty;
        const float* Ag = Ks + g*MSK;
        const float* Vr = Vs + c*MSV;
        float o = 0.f;
        #pragma unroll 8
        for (int m = 0; m < NM; m++) o += Ag[m] * Vr[m];
        out[b*262144 + (g*32 + px)*1024 + py*32 + c] = o;
    }
}

// ---------------- launch ----------------
extern "C" void kernel_launch(void* const* d_in, const int* in_sizes, int n_in,
                              void* d_out, int out_size) {
    const float* x   = (const float*)d_in[0];
    const float* wq  = (const float*)d_in[1];
    const float* bq  = (const float*)d_in[2];
    const float* wk  = (const float*)d_in[3];
    const float* bk  = (const float*)d_in[4];
    const float* wv  = (const float*)d_in[5];
    const float* bv  = (const float*)d_in[6];
    const float* rlh = (const float*)d_in[7];
    const float* rlw = (const float*)d_in[8];
    float* out = (float*)d_out;

    qconv_kernel<<<NB*NPIX, 256>>>(x, wq, bq);
    kvconv_kernel<<<NB*HP*HP, 256>>>(x, wk, bk, wv, bv);
    cudaFuncSetAttribute(attn_kernel, cudaFuncAttributeMaxDynamicSharedMemorySize, ATTN_SMEM);
    attn_kernel<<<NB*NPIX, 256, ATTN_SMEM>>>(rlh, rlw, out);
}